// round 4
// baseline (speedup 1.0000x reference)
#include <cuda_runtime.h>
#include <cuda_bf16.h>
#include <math.h>

#define Bz   2
#define Cc   512
#define Tt   16
#define HWp  1024
#define EPS  1e-5f
#define SCALE 0.04419417382415922f  // 512^-0.5
#define FULLMASK 0xffffffffu
#define STR  516
#define KSTR 68
#define VSTR 132
#define SSTR 68

typedef unsigned long long ull;

// ---------------- f32x2 helpers ----------------
__device__ __forceinline__ ull pack2(float v) {
    ull r; asm("mov.b64 %0, {%1, %1};" : "=l"(r) : "f"(v)); return r;
}
__device__ __forceinline__ void fma2(ull& a, ull x, ull y) {
    asm("fma.rn.f32x2 %0, %1, %2, %0;" : "+l"(a) : "l"(x), "l"(y));
}
__device__ __forceinline__ float2 unpack2(ull v) {
    float2 f; asm("mov.b64 {%0, %1}, %2;" : "=f"(f.x), "=f"(f.y) : "l"(v)); return f;
}

// ---------------- scratch ----------------
__device__ float g_mu  [Bz * 32 * Tt];
__device__ float g_rstd[Bz * 32 * Tt];
__device__ float g_kv  [128 * 1024];      // [b*64+s][2C]
__device__ float g_kpT [512 * 128];       // [c][b*64+s]
__device__ float g_vp  [128 * 512];       // [b*64+s][c]
__device__ float g_ksb [128];

// ---------------- groupnorm stats ----------------
__global__ void gn_stats_kernel(const float* __restrict__ x) {
    int idx = blockIdx.x;                 // b*512 + g*16 + t
    int b = idx >> 9, g = (idx >> 4) & 31, t = idx & 15;
    int tid = threadIdx.x;
    float s = 0.f, sq = 0.f;
    for (int ci = 0; ci < 16; ci++) {
        const float4* row = (const float4*)(x + (size_t)(((b*Cc + g*16 + ci)*Tt + t)) * HWp);
        float4 v = row[tid];
        s  += v.x + v.y + v.z + v.w;
        sq += v.x*v.x + v.y*v.y + v.z*v.z + v.w*v.w;
    }
    __shared__ float s1[256], s2[256];
    s1[tid] = s; s2[tid] = sq;
    __syncthreads();
    for (int st = 128; st > 0; st >>= 1) {
        if (tid < st) { s1[tid] += s1[tid + st]; s2[tid] += s2[tid + st]; }
        __syncthreads();
    }
    if (tid == 0) {
        const float invN = 1.f / 16384.f;
        float mu  = s1[0] * invN;
        float var = s2[0] * invN - mu * mu;
        g_mu[idx] = mu;
        g_rstd[idx] = rsqrtf(var + EPS);
    }
}

// ---------------- seed ----------------
__global__ void seed_kernel(const float* __restrict__ bkv) {
    int i = blockIdx.x * 256 + threadIdx.x;
    if (i < 131072)       g_kv[i]         = bkv[i & 1023];
    else if (i < 196608)  g_kpT[i-131072] = 0.f;
    else                  g_vp[i-196608]  = 0.f;
}

// ---------------- kv = context @ wkv^T (split-K, atomic) ----------------
__global__ void kv_gemm(const float* __restrict__ A, const float* __restrict__ B) {
    __shared__ float As[16][68];
    __shared__ float Bs[16][68];
    int m0 = blockIdx.y * 64, n0 = blockIdx.x * 64;
    int k0base = blockIdx.z * 256;
    int tid = threadIdx.x;
    int tx = tid & 15, ty = tid >> 4;

    float acc[4][4];
    #pragma unroll
    for (int i = 0; i < 4; i++)
        #pragma unroll
        for (int j = 0; j < 4; j++) acc[i][j] = 0.f;

    for (int k0 = k0base; k0 < k0base + 256; k0 += 16) {
        {
            int mm = tid >> 2, kb = (tid & 3) << 2;
            float4 av = *(const float4*)&A[(size_t)(m0 + mm) * 1024 + k0 + kb];
            As[kb+0][mm] = av.x; As[kb+1][mm] = av.y;
            As[kb+2][mm] = av.z; As[kb+3][mm] = av.w;
        }
        {   // B^T: B row-major [N,K]
            int nn = tid >> 2, kb = (tid & 3) << 2;
            float4 bv = *(const float4*)&B[(size_t)(n0 + nn) * 1024 + k0 + kb];
            Bs[kb+0][nn] = bv.x; Bs[kb+1][nn] = bv.y;
            Bs[kb+2][nn] = bv.z; Bs[kb+3][nn] = bv.w;
        }
        __syncthreads();
        #pragma unroll
        for (int kk = 0; kk < 16; kk++) {
            float4 a4 = *(const float4*)&As[kk][ty << 2];
            float4 b4 = *(const float4*)&Bs[kk][tx << 2];
            float a[4] = {a4.x, a4.y, a4.z, a4.w};
            float bb[4] = {b4.x, b4.y, b4.z, b4.w};
            #pragma unroll
            for (int i = 0; i < 4; i++)
                #pragma unroll
                for (int j = 0; j < 4; j++)
                    acc[i][j] += a[i] * bb[j];
        }
        __syncthreads();
    }
    #pragma unroll
    for (int i = 0; i < 4; i++)
        #pragma unroll
        for (int j = 0; j < 4; j++)
            atomicAdd(&g_kv[(size_t)(m0 + (ty<<2) + i) * 1024 + n0 + (tx<<2) + j], acc[i][j]);
}

// ---------------- proj2: kT gemm (0-31), vp gemm (32-63), ksb (64-67) ----------------
__global__ void proj2_kernel(const float* __restrict__ wq, const float* __restrict__ wo,
                             const float* __restrict__ bq) {
    int bid = blockIdx.x;
    int tid = threadIdx.x;

    if (bid >= 64) {          // ksb: bq . k  (32 rows per block, warp handles 4 rows)
        int warp = tid >> 5, lane = tid & 31;
        int base = (bid - 64) * 32 + warp * 4;
        for (int r = 0; r < 4; r++) {
            int row = base + r;
            const float4* kr = (const float4*)&g_kv[(size_t)row * 1024];
            float s = 0.f;
            #pragma unroll
            for (int i = 0; i < 4; i++) {
                float4 kvv = kr[i*32 + lane];
                float4 bqv = *(const float4*)&bq[(i*32 + lane) << 2];
                s += kvv.x*bqv.x + kvv.y*bqv.y + kvv.z*bqv.z + kvv.w*bqv.w;
            }
            #pragma unroll
            for (int off = 16; off > 0; off >>= 1) s += __shfl_xor_sync(FULLMASK, s, off);
            if (lane == 0) g_ksb[row] = s;
        }
        return;
    }

    __shared__ float As[16][68];
    __shared__ float Bs[16][68];
    bool isK = bid < 32;
    int local = bid & 31;
    int n0 = (local & 7) * 64;
    int m0 = ((local >> 3) & 1) * 64;
    int k0base = (local >> 4) * 256;
    const float* A = isK ? g_kv : (g_kv + 512);
    const float* B = isK ? wq : wo;
    int tx = tid & 15, ty = tid >> 4;

    float acc[4][4];
    #pragma unroll
    for (int i = 0; i < 4; i++)
        #pragma unroll
        for (int j = 0; j < 4; j++) acc[i][j] = 0.f;

    for (int k0 = k0base; k0 < k0base + 256; k0 += 16) {
        {
            int mm = tid >> 2, kb = (tid & 3) << 2;
            float4 av = *(const float4*)&A[(size_t)(m0 + mm) * 1024 + k0 + kb];
            As[kb+0][mm] = av.x; As[kb+1][mm] = av.y;
            As[kb+2][mm] = av.z; As[kb+3][mm] = av.w;
        }
        if (isK) {            // B = wq, not transposed: Bs[k][n] = B[k*512 + n]
            int kk = tid >> 4, nb = (tid & 15) << 2;
            float4 bv = *(const float4*)&B[(size_t)(k0 + kk) * 512 + n0 + nb];
            *(float4*)&Bs[kk][nb] = bv;
        } else {              // B = wo^T
            int nn = tid >> 2, kb = (tid & 3) << 2;
            float4 bv = *(const float4*)&B[(size_t)(n0 + nn) * 512 + k0 + kb];
            Bs[kb+0][nn] = bv.x; Bs[kb+1][nn] = bv.y;
            Bs[kb+2][nn] = bv.z; Bs[kb+3][nn] = bv.w;
        }
        __syncthreads();
        #pragma unroll
        for (int kk = 0; kk < 16; kk++) {
            float4 a4 = *(const float4*)&As[kk][ty << 2];
            float4 b4 = *(const float4*)&Bs[kk][tx << 2];
            float a[4] = {a4.x, a4.y, a4.z, a4.w};
            float bb[4] = {b4.x, b4.y, b4.z, b4.w};
            #pragma unroll
            for (int i = 0; i < 4; i++)
                #pragma unroll
                for (int j = 0; j < 4; j++)
                    acc[i][j] += a[i] * bb[j];
        }
        __syncthreads();
    }
    #pragma unroll
    for (int i = 0; i < 4; i++)
        #pragma unroll
        for (int j = 0; j < 4; j++) {
            int m = m0 + (ty << 2) + i, n = n0 + (tx << 2) + j;
            if (isK) atomicAdd(&g_kpT[(size_t)n * 128 + m], acc[i][j]);   // transposed
            else     atomicAdd(&g_vp [(size_t)m * 512 + n], acc[i][j]);
        }
}

// ---------------- fused normalize + attention + residual ----------------
// block per (b, t, 32-hw tile); 256 threads; ~110KB smem -> 2 CTAs/SM
__global__ void __launch_bounds__(256) attn_kernel(
    const float* __restrict__ x, const float* __restrict__ gamma,
    const float* __restrict__ beta, const float* __restrict__ bo,
    float* __restrict__ out) {
    extern __shared__ float sh[];
    float* sh_h = sh;                      // 32 x STR
    float* sh_k = sh + 32 * STR;           // kT 128xKSTR  /  v 64xVSTR
    float* sh_s = sh_k + 128 * KSTR;       // 32 x SSTR

    int bi = blockIdx.x;
    int tile = bi & 31, t = 15 - ((bi >> 5) & 15), b = bi >> 9;
    int hw0 = tile * 32;
    int tid = threadIdx.x;
    const int L = (t + 1) * 4;

    // ---- stage normalized h[hw][c] ----
    {
        const float* mub = g_mu   + b * 512 + t;
        const float* rsb = g_rstd + b * 512 + t;
        #pragma unroll
        for (int it = 0; it < 16; it++) {
            int lin = it * 256 + tid;        // 0..4095
            int c  = lin >> 3;
            int hw = (lin & 7) << 2;
            float4 xv = *(const float4*)(x + (size_t)(((b*Cc + c)*Tt + t)) * HWp + hw0 + hw);
            int g = c >> 4;
            float scl = rsb[g * 16] * gamma[c];
            float bia = beta[c] - mub[g * 16] * scl;
            sh_h[(hw+0)*STR + c] = xv.x * scl + bia;
            sh_h[(hw+1)*STR + c] = xv.y * scl + bia;
            sh_h[(hw+2)*STR + c] = xv.z * scl + bia;
            sh_h[(hw+3)*STR + c] = xv.w * scl + bia;
        }
    }
    __syncthreads();

    int warp = tid >> 5, lane = tid & 31;

    // ================= scores: S = h @ kT (f32x2) =================
    {
        int qw = warp >> 2, sw = warp & 3;
        int q0 = qw * 16, s0 = sw * 16;
        int ly = lane >> 2, lx = lane & 3;
        ull a00 = 0, a01 = 0, a10 = 0, a11 = 0;   // 2 rows x 2 pairs
        bool active = (s0 < L);

        for (int c0 = 0; c0 < 512; c0 += 128) {
            // load kT chunk (L-aware)
            #pragma unroll
            for (int i = 0; i < 8; i++) {
                int idx = i * 256 + tid;           // 0..2047 float4 units
                int cc = idx >> 4, sf = (idx & 15) << 2;
                if (sf < L) {
                    float4 v = *(const float4*)&g_kpT[(size_t)(c0 + cc) * 128 + b * 64 + sf];
                    *(float4*)&sh_k[cc * KSTR + sf] = v;
                }
            }
            __syncthreads();
            if (active) {
                #pragma unroll 2
                for (int c = 0; c < 128; c += 4) {
                    float4 h0 = *(const float4*)&sh_h[(q0 + ly    ) * STR + c0 + c];
                    float4 h1 = *(const float4*)&sh_h[(q0 + ly + 8) * STR + c0 + c];
                    const float* kb = &sh_k[c * KSTR + s0 + (lx << 2)];
                    ulonglong2 b0 = *(const ulonglong2*)(kb);
                    ulonglong2 b1 = *(const ulonglong2*)(kb + KSTR);
                    ulonglong2 b2 = *(const ulonglong2*)(kb + 2*KSTR);
                    ulonglong2 b3 = *(const ulonglong2*)(kb + 3*KSTR);
                    ull p;
                    p = pack2(h0.x); fma2(a00, p, b0.x); fma2(a01, p, b0.y);
                    p = pack2(h1.x); fma2(a10, p, b0.x); fma2(a11, p, b0.y);
                    p = pack2(h0.y); fma2(a00, p, b1.x); fma2(a01, p, b1.y);
                    p = pack2(h1.y); fma2(a10, p, b1.x); fma2(a11, p, b1.y);
                    p = pack2(h0.z); fma2(a00, p, b2.x); fma2(a01, p, b2.y);
                    p = pack2(h1.z); fma2(a10, p, b2.x); fma2(a11, p, b2.y);
                    p = pack2(h0.w); fma2(a00, p, b3.x); fma2(a01, p, b3.y);
                    p = pack2(h1.w); fma2(a10, p, b3.x); fma2(a11, p, b3.y);
                }
            }
            __syncthreads();
        }
        if (active) {
            const float* ksbb = g_ksb + b * 64;
            float2 r00 = unpack2(a00), r01 = unpack2(a01);
            float2 r10 = unpack2(a10), r11 = unpack2(a11);
            float sc0[4] = {r00.x, r00.y, r01.x, r01.y};
            float sc1[4] = {r10.x, r10.y, r11.x, r11.y};
            #pragma unroll
            for (int j = 0; j < 4; j++) {
                int s = s0 + (lx << 2) + j;
                if (s < L) {
                    float kb = ksbb[s];
                    sh_s[(q0 + ly    ) * SSTR + s] = (sc0[j] + kb) * SCALE;
                    sh_s[(q0 + ly + 8) * SSTR + s] = (sc1[j] + kb) * SCALE;
                }
            }
        }
    }
    __syncthreads();

    // ================= softmax (warp = 4 rows) =================
    for (int r = 0; r < 4; r++) {
        int q = warp * 4 + r;
        float v0 = (lane      < L) ? sh_s[q * SSTR + lane     ] : -INFINITY;
        float v1 = (lane + 32 < L) ? sh_s[q * SSTR + lane + 32] : -INFINITY;
        float mx = fmaxf(v0, v1);
        #pragma unroll
        for (int off = 16; off > 0; off >>= 1) mx = fmaxf(mx, __shfl_xor_sync(FULLMASK, mx, off));
        float e0 = __expf(v0 - mx), e1 = __expf(v1 - mx);
        float ds = e0 + e1;
        #pragma unroll
        for (int off = 16; off > 0; off >>= 1) ds += __shfl_xor_sync(FULLMASK, ds, off);
        float inv = 1.f / ds;
        if (lane      < L) sh_s[q * SSTR + lane     ] = e0 * inv;
        if (lane + 32 < L) sh_s[q * SSTR + lane + 32] = e1 * inv;
    }

    // ================= combine: O = W @ v' (f32x2) =================
    {
        int qw = warp >> 2, cw = warp & 3;
        int q0 = qw * 16;
        int ly2 = lane >> 3, lx2 = lane & 7;
        int coff = cw * 32 + (lx2 << 2);

        for (int c0 = 0; c0 < 512; c0 += 128) {
            __syncthreads();
            #pragma unroll
            for (int i = 0; i < 8; i++) {
                int idx = i * 256 + tid;            // 0..2047 float4 units
                int s = idx >> 5, col = (idx & 31) << 2;
                if (s < L) {
                    float4 v = *(const float4*)&g_vp[(size_t)(b * 64 + s) * 512 + c0 + col];
                    *(float4*)&sh_k[s * VSTR + col] = v;
                }
            }
            __syncthreads();

            ull acc[4][2];
            #pragma unroll
            for (int k = 0; k < 4; k++) { acc[k][0] = 0; acc[k][1] = 0; }

            for (int s = 0; s < L; s += 2) {
                ulonglong2 va = *(const ulonglong2*)&sh_k[ s      * VSTR + coff];
                ulonglong2 vb = *(const ulonglong2*)&sh_k[(s + 1) * VSTR + coff];
                #pragma unroll
                for (int k = 0; k < 4; k++) {
                    float2 w = *(const float2*)&sh_s[(q0 + ly2 + 4*k) * SSTR + s];
                    ull p;
                    p = pack2(w.x); fma2(acc[k][0], p, va.x); fma2(acc[k][1], p, va.y);
                    p = pack2(w.y); fma2(acc[k][0], p, vb.x); fma2(acc[k][1], p, vb.y);
                }
            }
            #pragma unroll
            for (int k = 0; k < 4; k++) {
                float2 f0 = unpack2(acc[k][0]), f1 = unpack2(acc[k][1]);
                float4 r; r.x = f0.x; r.y = f0.y; r.z = f1.x; r.w = f1.y;
                *(float4*)&sh_h[(q0 + ly2 + 4*k) * STR + c0 + coff] = r;
            }
        }
    }
    __syncthreads();

    // ---- out = x + o + bo ----
    #pragma unroll
    for (int it = 0; it < 64; it++) {
        int lin = it * 256 + tid;
        int c = lin >> 5, hw = lin & 31;
        size_t gidx = (size_t)(((b*Cc + c)*Tt + t)) * HWp + hw0 + hw;
        out[gidx] = x[gidx] + sh_h[hw * STR + c] + bo[c];
    }
}

// ---------------- launch ----------------
extern "C" void kernel_launch(void* const* d_in, const int* in_sizes, int n_in,
                              void* d_out, int out_size) {
    const float* x       = (const float*)d_in[0];
    const float* context = (const float*)d_in[1];
    const float* gamma   = (const float*)d_in[2];
    const float* beta    = (const float*)d_in[3];
    const float* wq      = (const float*)d_in[4];
    const float* bq      = (const float*)d_in[5];
    const float* wkv     = (const float*)d_in[6];
    const float* bkv     = (const float*)d_in[7];
    const float* wo      = (const float*)d_in[8];
    const float* bo      = (const float*)d_in[9];
    float* out = (float*)d_out;

    const int SMEM_BYTES = (32*STR + 128*KSTR + 32*SSTR) * 4;   // 109568
    static bool attr_set = false;
    cudaFuncSetAttribute(attn_kernel, cudaFuncAttributeMaxDynamicSharedMemorySize, SMEM_BYTES);
    (void)attr_set;

    seed_kernel<<<1024, 256>>>(bkv);
    gn_stats_kernel<<<1024, 256>>>(x);
    kv_gemm<<<dim3(16, 2, 4), 256>>>(context, wkv);
    proj2_kernel<<<68, 256>>>(wq, wo, bq);
    attn_kernel<<<Bz * Tt * 32, 256, SMEM_BYTES>>>(x, gamma, beta, bo, out);
}

// round 5
// speedup vs baseline: 1.3943x; 1.3943x over previous
#include <cuda_runtime.h>
#include <cuda_bf16.h>
#include <math.h>

#define Bz   2
#define Cc   512
#define Tt   16
#define HWp  1024
#define EPS  1e-5f
#define SCALE 0.04419417382415922f  // 512^-0.5
#define FULLMASK 0xffffffffu
#define STR  516
#define KSTR 72     // kT chunk stride (72 mod 32 = 8 -> conflict-free B frags)
#define VSTR 136    // v chunk stride  (136 mod 32 = 8)
#define SSTR 68     // score stride    (68 mod 32 = 4 -> conflict-free A frags)

typedef unsigned int uint;

// ---------------- tf32 helpers ----------------
__device__ __forceinline__ uint tf32r(float f) {
    uint r; asm("cvt.rna.tf32.f32 %0, %1;" : "=r"(r) : "f"(f)); return r;
}
__device__ __forceinline__ void mma_tf32(float4& d, uint a0, uint a1, uint a2, uint a3,
                                         uint b0, uint b1) {
    asm volatile("mma.sync.aligned.m16n8k8.row.col.f32.tf32.tf32.f32 "
                 "{%0,%1,%2,%3}, {%4,%5,%6,%7}, {%8,%9}, {%0,%1,%2,%3};"
                 : "+f"(d.x), "+f"(d.y), "+f"(d.z), "+f"(d.w)
                 : "r"(a0), "r"(a1), "r"(a2), "r"(a3), "r"(b0), "r"(b1));
}

// ---------------- scratch ----------------
__device__ float g_mu  [Bz * 32 * Tt];
__device__ float g_rstd[Bz * 32 * Tt];
__device__ float g_kv  [128 * 1024];      // [b*64+s][2C]
__device__ float g_kpT [512 * 128];       // [c][b*64+s]
__device__ float g_vp  [128 * 512];       // [b*64+s][c]
__device__ float g_ksb [128];

// ---------------- groupnorm stats ----------------
__global__ void gn_stats_kernel(const float* __restrict__ x) {
    int idx = blockIdx.x;                 // b*512 + g*16 + t
    int b = idx >> 9, g = (idx >> 4) & 31, t = idx & 15;
    int tid = threadIdx.x;
    float s = 0.f, sq = 0.f;
    for (int ci = 0; ci < 16; ci++) {
        const float4* row = (const float4*)(x + (size_t)(((b*Cc + g*16 + ci)*Tt + t)) * HWp);
        float4 v = row[tid];
        s  += v.x + v.y + v.z + v.w;
        sq += v.x*v.x + v.y*v.y + v.z*v.z + v.w*v.w;
    }
    __shared__ float s1[256], s2[256];
    s1[tid] = s; s2[tid] = sq;
    __syncthreads();
    for (int st = 128; st > 0; st >>= 1) {
        if (tid < st) { s1[tid] += s1[tid + st]; s2[tid] += s2[tid + st]; }
        __syncthreads();
    }
    if (tid == 0) {
        const float invN = 1.f / 16384.f;
        float mu  = s1[0] * invN;
        float var = s2[0] * invN - mu * mu;
        g_mu[idx] = mu;
        g_rstd[idx] = rsqrtf(var + EPS);
    }
}

// ---------------- seed ----------------
__global__ void seed_kernel(const float* __restrict__ bkv) {
    int i = blockIdx.x * 256 + threadIdx.x;
    if (i < 131072)       g_kv[i]         = bkv[i & 1023];
    else if (i < 196608)  g_kpT[i-131072] = 0.f;
    else                  g_vp[i-196608]  = 0.f;
}

// ---------------- kv = context @ wkv^T (split-K 8, atomic) ----------------
__global__ void kv_gemm(const float* __restrict__ A, const float* __restrict__ B) {
    __shared__ float As[16][68];
    __shared__ float Bs[16][68];
    int m0 = blockIdx.y * 64, n0 = blockIdx.x * 64;
    int k0base = blockIdx.z * 128;
    int tid = threadIdx.x;
    int tx = tid & 15, ty = tid >> 4;

    float acc[4][4];
    #pragma unroll
    for (int i = 0; i < 4; i++)
        #pragma unroll
        for (int j = 0; j < 4; j++) acc[i][j] = 0.f;

    for (int k0 = k0base; k0 < k0base + 128; k0 += 16) {
        {
            int mm = tid >> 2, kb = (tid & 3) << 2;
            float4 av = *(const float4*)&A[(size_t)(m0 + mm) * 1024 + k0 + kb];
            As[kb+0][mm] = av.x; As[kb+1][mm] = av.y;
            As[kb+2][mm] = av.z; As[kb+3][mm] = av.w;
        }
        {
            int nn = tid >> 2, kb = (tid & 3) << 2;
            float4 bv = *(const float4*)&B[(size_t)(n0 + nn) * 1024 + k0 + kb];
            Bs[kb+0][nn] = bv.x; Bs[kb+1][nn] = bv.y;
            Bs[kb+2][nn] = bv.z; Bs[kb+3][nn] = bv.w;
        }
        __syncthreads();
        #pragma unroll
        for (int kk = 0; kk < 16; kk++) {
            float4 a4 = *(const float4*)&As[kk][ty << 2];
            float4 b4 = *(const float4*)&Bs[kk][tx << 2];
            float a[4] = {a4.x, a4.y, a4.z, a4.w};
            float bb[4] = {b4.x, b4.y, b4.z, b4.w};
            #pragma unroll
            for (int i = 0; i < 4; i++)
                #pragma unroll
                for (int j = 0; j < 4; j++)
                    acc[i][j] += a[i] * bb[j];
        }
        __syncthreads();
    }
    #pragma unroll
    for (int i = 0; i < 4; i++)
        #pragma unroll
        for (int j = 0; j < 4; j++)
            atomicAdd(&g_kv[(size_t)(m0 + (ty<<2) + i) * 1024 + n0 + (tx<<2) + j], acc[i][j]);
}

// ---------------- proj2: kT (0-63), vp (64-127), ksb (128-131) ----------------
__global__ void proj2_kernel(const float* __restrict__ wq, const float* __restrict__ wo,
                             const float* __restrict__ bq) {
    int bid = blockIdx.x;
    int tid = threadIdx.x;

    if (bid >= 128) {         // ksb: bq . k
        int warp = tid >> 5, lane = tid & 31;
        int base = (bid - 128) * 32 + warp * 4;
        for (int r = 0; r < 4; r++) {
            int row = base + r;
            const float4* kr = (const float4*)&g_kv[(size_t)row * 1024];
            float s = 0.f;
            #pragma unroll
            for (int i = 0; i < 4; i++) {
                float4 kvv = kr[i*32 + lane];
                float4 bqv = *(const float4*)&bq[(i*32 + lane) << 2];
                s += kvv.x*bqv.x + kvv.y*bqv.y + kvv.z*bqv.z + kvv.w*bqv.w;
            }
            #pragma unroll
            for (int off = 16; off > 0; off >>= 1) s += __shfl_xor_sync(FULLMASK, s, off);
            if (lane == 0) g_ksb[row] = s;
        }
        return;
    }

    __shared__ float As[16][68];
    __shared__ float Bs[16][68];
    bool isK = bid < 64;
    int local = bid & 63;
    int n0 = (local & 7) * 64;
    int m0 = ((local >> 3) & 1) * 64;
    int k0base = (local >> 4) * 128;        // split-K 4
    const float* A = isK ? g_kv : (g_kv + 512);
    const float* B = isK ? wq : wo;
    int tx = tid & 15, ty = tid >> 4;

    float acc[4][4];
    #pragma unroll
    for (int i = 0; i < 4; i++)
        #pragma unroll
        for (int j = 0; j < 4; j++) acc[i][j] = 0.f;

    for (int k0 = k0base; k0 < k0base + 128; k0 += 16) {
        {
            int mm = tid >> 2, kb = (tid & 3) << 2;
            float4 av = *(const float4*)&A[(size_t)(m0 + mm) * 1024 + k0 + kb];
            As[kb+0][mm] = av.x; As[kb+1][mm] = av.y;
            As[kb+2][mm] = av.z; As[kb+3][mm] = av.w;
        }
        if (isK) {            // B = wq: Bs[k][n] = B[k*512 + n]
            int kk = tid >> 4, nb = (tid & 15) << 2;
            float4 bv = *(const float4*)&B[(size_t)(k0 + kk) * 512 + n0 + nb];
            *(float4*)&Bs[kk][nb] = bv;
        } else {              // B = wo^T
            int nn = tid >> 2, kb = (tid & 3) << 2;
            float4 bv = *(const float4*)&B[(size_t)(n0 + nn) * 512 + k0 + kb];
            Bs[kb+0][nn] = bv.x; Bs[kb+1][nn] = bv.y;
            Bs[kb+2][nn] = bv.z; Bs[kb+3][nn] = bv.w;
        }
        __syncthreads();
        #pragma unroll
        for (int kk = 0; kk < 16; kk++) {
            float4 a4 = *(const float4*)&As[kk][ty << 2];
            float4 b4 = *(const float4*)&Bs[kk][tx << 2];
            float a[4] = {a4.x, a4.y, a4.z, a4.w};
            float bb[4] = {b4.x, b4.y, b4.z, b4.w};
            #pragma unroll
            for (int i = 0; i < 4; i++)
                #pragma unroll
                for (int j = 0; j < 4; j++)
                    acc[i][j] += a[i] * bb[j];
        }
        __syncthreads();
    }
    #pragma unroll
    for (int i = 0; i < 4; i++)
        #pragma unroll
        for (int j = 0; j < 4; j++) {
            int m = m0 + (ty << 2) + i, n = n0 + (tx << 2) + j;
            if (isK) atomicAdd(&g_kpT[(size_t)n * 128 + m], acc[i][j]);
            else     atomicAdd(&g_vp [(size_t)m * 512 + n], acc[i][j]);
        }
}

// ---------------- fused normalize + attention (tf32 mma) + residual ----------------
// block per (b, t, 32-hw tile); 256 threads (8 warps); ~109KB smem -> 2 CTAs/SM
__global__ void __launch_bounds__(256) attn_kernel(
    const float* __restrict__ x, const float* __restrict__ gamma,
    const float* __restrict__ beta, const float* __restrict__ bo,
    float* __restrict__ out) {
    extern __shared__ float sh[];
    float* sh_hf = sh;                       // 32 x STR  (h tf32, later o fp32)
    uint*  sh_hu = (uint*)sh;
    float* sh_kf = sh + 32 * STR;            // kT 128xKSTR / v 64xVSTR (tf32)
    uint*  sh_ku = (uint*)sh_kf;
    float* sh_sf = sh_kf + 128 * KSTR;       // 32 x SSTR (scores fp32 -> weights tf32)
    uint*  sh_su = (uint*)sh_sf;
    __shared__ float sksb[64];

    int bi = blockIdx.x;
    int tile = bi & 31, t = 15 - ((bi >> 5) & 15), b = bi >> 9;
    int hw0 = tile * 32;
    int tid = threadIdx.x;
    const int L  = (t + 1) * 4;
    const int L8 = (L + 7) & ~7;

    // ---- prefetch kT chunk 0 into registers ----
    float4 pre[8];
    #pragma unroll
    for (int i = 0; i < 8; i++) {
        int idx = i * 256 + tid;
        int cc = idx >> 4, sf = (idx & 15) << 2;
        if (sf < L8) pre[i] = *(const float4*)&g_kpT[(size_t)cc * 128 + b * 64 + sf];
    }
    if (tid < 64) sksb[tid] = g_ksb[b * 64 + tid];

    // ---- stage normalized h (tf32) ----
    {
        const float* mub = g_mu   + b * 512 + t;
        const float* rsb = g_rstd + b * 512 + t;
        #pragma unroll
        for (int it = 0; it < 16; it++) {
            int lin = it * 256 + tid;
            int c  = lin >> 3;
            int hw = (lin & 7) << 2;
            float4 xv = *(const float4*)(x + (size_t)(((b*Cc + c)*Tt + t)) * HWp + hw0 + hw);
            int g = c >> 4;
            float scl = rsb[g * 16] * gamma[c];
            float bia = beta[c] - mub[g * 16] * scl;
            sh_hu[(hw+0)*STR + c] = tf32r(xv.x * scl + bia);
            sh_hu[(hw+1)*STR + c] = tf32r(xv.y * scl + bia);
            sh_hu[(hw+2)*STR + c] = tf32r(xv.z * scl + bia);
            sh_hu[(hw+3)*STR + c] = tf32r(xv.w * scl + bia);
        }
    }
    __syncthreads();

    int warp = tid >> 5, lane = tid & 31;
    int grp = lane >> 2, tig = lane & 3;

    // ================= scores: S = h @ kT (tf32 mma) =================
    {
        int qw = warp >> 2, sw = warp & 3;
        int q0 = qw * 16;
        int s0a = sw * 16, s0b = sw * 16 + 8;
        bool act0 = s0a < L, act1 = s0b < L;
        float4 C0 = {0,0,0,0}, C1 = {0,0,0,0};

        for (int ch = 0; ch < 4; ch++) {
            // store prefetched kT chunk (tf32)
            #pragma unroll
            for (int i = 0; i < 8; i++) {
                int idx = i * 256 + tid;
                int cc = idx >> 4, sf = (idx & 15) << 2;
                if (sf < L8) {
                    sh_ku[cc*KSTR + sf + 0] = tf32r(pre[i].x);
                    sh_ku[cc*KSTR + sf + 1] = tf32r(pre[i].y);
                    sh_ku[cc*KSTR + sf + 2] = tf32r(pre[i].z);
                    sh_ku[cc*KSTR + sf + 3] = tf32r(pre[i].w);
                }
            }
            __syncthreads();
            // prefetch next chunk (kT ch+1, or v chunk 0 on last)
            if (ch < 3) {
                #pragma unroll
                for (int i = 0; i < 8; i++) {
                    int idx = i * 256 + tid;
                    int cc = idx >> 4, sf = (idx & 15) << 2;
                    if (sf < L8)
                        pre[i] = *(const float4*)&g_kpT[(size_t)(128*(ch+1) + cc) * 128 + b * 64 + sf];
                }
            } else {
                #pragma unroll
                for (int i = 0; i < 8; i++) {
                    int idx = i * 256 + tid;
                    int s = idx >> 5, col = (idx & 31) << 2;
                    if (s < L8)
                        pre[i] = *(const float4*)&g_vp[(size_t)(b * 64 + s) * 512 + col];
                }
            }
            if (act0) {
                int c0 = ch * 128;
                #pragma unroll
                for (int k8 = 0; k8 < 16; k8++) {
                    int cb = k8 * 8;
                    uint a0 = sh_hu[(q0+grp  )*STR + c0 + cb + tig];
                    uint a1 = sh_hu[(q0+grp+8)*STR + c0 + cb + tig];
                    uint a2 = sh_hu[(q0+grp  )*STR + c0 + cb + tig + 4];
                    uint a3 = sh_hu[(q0+grp+8)*STR + c0 + cb + tig + 4];
                    uint b0 = sh_ku[(cb+tig  )*KSTR + s0a + grp];
                    uint b1 = sh_ku[(cb+tig+4)*KSTR + s0a + grp];
                    mma_tf32(C0, a0, a1, a2, a3, b0, b1);
                    if (act1) {
                        uint b2 = sh_ku[(cb+tig  )*KSTR + s0b + grp];
                        uint b3 = sh_ku[(cb+tig+4)*KSTR + s0b + grp];
                        mma_tf32(C1, a0, a1, a2, a3, b2, b3);
                    }
                }
            }
            __syncthreads();
        }
        // epilogue -> sh_s (fp32, +bias, *scale)
        if (act0) {
            int s = s0a + 2 * tig;
            if (s < L) {
                float kb = sksb[s];
                sh_sf[(q0+grp  )*SSTR + s] = (C0.x + kb) * SCALE;
                sh_sf[(q0+grp+8)*SSTR + s] = (C0.z + kb) * SCALE;
            }
            if (s + 1 < L) {
                float kb = sksb[s+1];
                sh_sf[(q0+grp  )*SSTR + s + 1] = (C0.y + kb) * SCALE;
                sh_sf[(q0+grp+8)*SSTR + s + 1] = (C0.w + kb) * SCALE;
            }
            if (act1) {
                int s2 = s0b + 2 * tig;
                if (s2 < L) {
                    float kb = sksb[s2];
                    sh_sf[(q0+grp  )*SSTR + s2] = (C1.x + kb) * SCALE;
                    sh_sf[(q0+grp+8)*SSTR + s2] = (C1.z + kb) * SCALE;
                }
                if (s2 + 1 < L) {
                    float kb = sksb[s2+1];
                    sh_sf[(q0+grp  )*SSTR + s2 + 1] = (C1.y + kb) * SCALE;
                    sh_sf[(q0+grp+8)*SSTR + s2 + 1] = (C1.w + kb) * SCALE;
                }
            }
        }
    }
    __syncthreads();

    // ================= softmax (warp = 4 rows), write tf32 weights =================
    for (int r = 0; r < 4; r++) {
        int q = warp * 4 + r;
        float v0 = (lane      < L) ? sh_sf[q * SSTR + lane     ] : -INFINITY;
        float v1 = (lane + 32 < L) ? sh_sf[q * SSTR + lane + 32] : -INFINITY;
        float mx = fmaxf(v0, v1);
        #pragma unroll
        for (int off = 16; off > 0; off >>= 1) mx = fmaxf(mx, __shfl_xor_sync(FULLMASK, mx, off));
        float e0 = __expf(v0 - mx), e1 = __expf(v1 - mx);
        float ds = e0 + e1;
        #pragma unroll
        for (int off = 16; off > 0; off >>= 1) ds += __shfl_xor_sync(FULLMASK, ds, off);
        float inv = 1.f / ds;
        if (lane      < L8) sh_su[q * SSTR + lane     ] = (lane      < L) ? tf32r(e0 * inv) : 0u;
        if (lane + 32 < L8) sh_su[q * SSTR + lane + 32] = (lane + 32 < L) ? tf32r(e1 * inv) : 0u;
    }
    __syncthreads();

    // ================= combine: O = W @ v' (tf32 mma) =================
    {
        int qw = warp >> 2, cw = warp & 3;
        int q0 = qw * 16;
        const int kmax = L8 >> 3;

        for (int ch = 0; ch < 4; ch++) {
            // store prefetched v chunk (tf32)
            #pragma unroll
            for (int i = 0; i < 8; i++) {
                int idx = i * 256 + tid;
                int s = idx >> 5, col = (idx & 31) << 2;
                if (s < L8) {
                    sh_ku[s*VSTR + col + 0] = tf32r(pre[i].x);
                    sh_ku[s*VSTR + col + 1] = tf32r(pre[i].y);
                    sh_ku[s*VSTR + col + 2] = tf32r(pre[i].z);
                    sh_ku[s*VSTR + col + 3] = tf32r(pre[i].w);
                }
            }
            __syncthreads();
            if (ch < 3) {
                #pragma unroll
                for (int i = 0; i < 8; i++) {
                    int idx = i * 256 + tid;
                    int s = idx >> 5, col = (idx & 31) << 2;
                    if (s < L8)
                        pre[i] = *(const float4*)&g_vp[(size_t)(b * 64 + s) * 512 + 128*(ch+1) + col];
                }
            }
            float4 D[4];
            #pragma unroll
            for (int nt = 0; nt < 4; nt++) D[nt] = make_float4(0.f, 0.f, 0.f, 0.f);

            #pragma unroll 4
            for (int k8 = 0; k8 < kmax; k8++) {
                int kb = k8 * 8;
                uint a0 = sh_su[(q0+grp  )*SSTR + kb + tig];
                uint a1 = sh_su[(q0+grp+8)*SSTR + kb + tig];
                uint a2 = sh_su[(q0+grp  )*SSTR + kb + tig + 4];
                uint a3 = sh_su[(q0+grp+8)*SSTR + kb + tig + 4];
                #pragma unroll
                for (int nt = 0; nt < 4; nt++) {
                    int n0 = cw * 32 + nt * 8;
                    uint b0 = sh_ku[(kb+tig  )*VSTR + n0 + grp];
                    uint b1 = sh_ku[(kb+tig+4)*VSTR + n0 + grp];
                    mma_tf32(D[nt], a0, a1, a2, a3, b0, b1);
                }
            }
            // epilogue -> sh_h (fp32 o)
            int c0 = ch * 128;
            #pragma unroll
            for (int nt = 0; nt < 4; nt++) {
                int col = cw * 32 + nt * 8 + 2 * tig;
                float2 r0 = {D[nt].x, D[nt].y};
                float2 r1 = {D[nt].z, D[nt].w};
                *(float2*)&sh_hf[(q0+grp  )*STR + c0 + col] = r0;
                *(float2*)&sh_hf[(q0+grp+8)*STR + c0 + col] = r1;
            }
            __syncthreads();
        }
    }

    // ---- out = x + o + bo ----
    #pragma unroll
    for (int it = 0; it < 64; it++) {
        int lin = it * 256 + tid;
        int c = lin >> 5, hw = lin & 31;
        size_t gidx = (size_t)(((b*Cc + c)*Tt + t)) * HWp + hw0 + hw;
        out[gidx] = x[gidx] + sh_hf[hw * STR + c] + bo[c];
    }
}

// ---------------- launch ----------------
extern "C" void kernel_launch(void* const* d_in, const int* in_sizes, int n_in,
                              void* d_out, int out_size) {
    const float* x       = (const float*)d_in[0];
    const float* context = (const float*)d_in[1];
    const float* gamma   = (const float*)d_in[2];
    const float* beta    = (const float*)d_in[3];
    const float* wq      = (const float*)d_in[4];
    const float* bq      = (const float*)d_in[5];
    const float* wkv     = (const float*)d_in[6];
    const float* bkv     = (const float*)d_in[7];
    const float* wo      = (const float*)d_in[8];
    const float* bo      = (const float*)d_in[9];
    float* out = (float*)d_out;

    const int SMEM_BYTES = (32*STR + 128*KSTR + 32*SSTR) * 4;   // 111616
    cudaFuncSetAttribute(attn_kernel, cudaFuncAttributeMaxDynamicSharedMemorySize, SMEM_BYTES);

    seed_kernel<<<1024, 256>>>(bkv);
    gn_stats_kernel<<<1024, 256>>>(x);
    kv_gemm<<<dim3(16, 2, 8), 256>>>(context, wkv);
    proj2_kernel<<<132, 256>>>(wq, wo, bq);
    attn_kernel<<<Bz * Tt * 32, 256, SMEM_BYTES>>>(x, gamma, beta, bo, out);
}

// round 6
// speedup vs baseline: 1.4088x; 1.0104x over previous
#include <cuda_runtime.h>
#include <cuda_bf16.h>
#include <math.h>

#define Bz   2
#define Cc   512
#define Tt   16
#define HWp  1024
#define EPS  1e-5f
#define SCALE 0.04419417382415922f  // 512^-0.5
#define FULLMASK 0xffffffffu
#define STR  516
#define KSTR 72     // kT chunk stride (72 mod 32 = 8 -> conflict-free B frags)
#define VSTR 136    // v chunk stride  (136 mod 32 = 8)
#define SSTR 68     // score stride    (68 mod 32 = 4 -> conflict-free A frags)

typedef unsigned int uint;

// ---------------- tf32 helpers ----------------
__device__ __forceinline__ uint tf32r(float f) {
    uint r; asm("cvt.rna.tf32.f32 %0, %1;" : "=r"(r) : "f"(f)); return r;
}
__device__ __forceinline__ void mma_tf32(float4& d, uint a0, uint a1, uint a2, uint a3,
                                         uint b0, uint b1) {
    asm volatile("mma.sync.aligned.m16n8k8.row.col.f32.tf32.tf32.f32 "
                 "{%0,%1,%2,%3}, {%4,%5,%6,%7}, {%8,%9}, {%0,%1,%2,%3};"
                 : "+f"(d.x), "+f"(d.y), "+f"(d.z), "+f"(d.w)
                 : "r"(a0), "r"(a1), "r"(a2), "r"(a3), "r"(b0), "r"(b1));
}

// ---------------- scratch ----------------
__device__ float g_mu  [Bz * 32 * Tt];
__device__ float g_rstd[Bz * 32 * Tt];
__device__ float g_kv  [128 * 1024];      // [b*64+s][2C]
__device__ float g_kpT [512 * 128];       // [c][b*64+s]
__device__ float g_vp  [128 * 512];       // [b*64+s][c]
__device__ float g_ksb [128];

// ---------------- groupnorm stats ----------------
__global__ void gn_stats_kernel(const float* __restrict__ x) {
    int idx = blockIdx.x;                 // b*512 + g*16 + t
    int b = idx >> 9, g = (idx >> 4) & 31, t = idx & 15;
    int tid = threadIdx.x;
    float s = 0.f, sq = 0.f;
    for (int ci = 0; ci < 16; ci++) {
        const float4* row = (const float4*)(x + (size_t)(((b*Cc + g*16 + ci)*Tt + t)) * HWp);
        float4 v = row[tid];
        s  += v.x + v.y + v.z + v.w;
        sq += v.x*v.x + v.y*v.y + v.z*v.z + v.w*v.w;
    }
    __shared__ float s1[256], s2[256];
    s1[tid] = s; s2[tid] = sq;
    __syncthreads();
    for (int st = 128; st > 0; st >>= 1) {
        if (tid < st) { s1[tid] += s1[tid + st]; s2[tid] += s2[tid + st]; }
        __syncthreads();
    }
    if (tid == 0) {
        const float invN = 1.f / 16384.f;
        float mu  = s1[0] * invN;
        float var = s2[0] * invN - mu * mu;
        g_mu[idx] = mu;
        g_rstd[idx] = rsqrtf(var + EPS);
    }
}

// ---------------- seed ----------------
__global__ void seed_kernel(const float* __restrict__ bkv) {
    int i = blockIdx.x * 256 + threadIdx.x;
    if (i < 131072)       g_kv[i]         = bkv[i & 1023];
    else if (i < 196608)  g_kpT[i-131072] = 0.f;
    else                  g_vp[i-196608]  = 0.f;
}

// ---------------- kv = context @ wkv^T (split-K 8, atomic) ----------------
__global__ void kv_gemm(const float* __restrict__ A, const float* __restrict__ B) {
    __shared__ float As[16][68];
    __shared__ float Bs[16][68];
    int m0 = blockIdx.y * 64, n0 = blockIdx.x * 64;
    int k0base = blockIdx.z * 128;
    int tid = threadIdx.x;
    int tx = tid & 15, ty = tid >> 4;

    float acc[4][4];
    #pragma unroll
    for (int i = 0; i < 4; i++)
        #pragma unroll
        for (int j = 0; j < 4; j++) acc[i][j] = 0.f;

    for (int k0 = k0base; k0 < k0base + 128; k0 += 16) {
        {
            int mm = tid >> 2, kb = (tid & 3) << 2;
            float4 av = *(const float4*)&A[(size_t)(m0 + mm) * 1024 + k0 + kb];
            As[kb+0][mm] = av.x; As[kb+1][mm] = av.y;
            As[kb+2][mm] = av.z; As[kb+3][mm] = av.w;
        }
        {
            int nn = tid >> 2, kb = (tid & 3) << 2;
            float4 bv = *(const float4*)&B[(size_t)(n0 + nn) * 1024 + k0 + kb];
            Bs[kb+0][nn] = bv.x; Bs[kb+1][nn] = bv.y;
            Bs[kb+2][nn] = bv.z; Bs[kb+3][nn] = bv.w;
        }
        __syncthreads();
        #pragma unroll
        for (int kk = 0; kk < 16; kk++) {
            float4 a4 = *(const float4*)&As[kk][ty << 2];
            float4 b4 = *(const float4*)&Bs[kk][tx << 2];
            float a[4] = {a4.x, a4.y, a4.z, a4.w};
            float bb[4] = {b4.x, b4.y, b4.z, b4.w};
            #pragma unroll
            for (int i = 0; i < 4; i++)
                #pragma unroll
                for (int j = 0; j < 4; j++)
                    acc[i][j] += a[i] * bb[j];
        }
        __syncthreads();
    }
    #pragma unroll
    for (int i = 0; i < 4; i++)
        #pragma unroll
        for (int j = 0; j < 4; j++)
            atomicAdd(&g_kv[(size_t)(m0 + (ty<<2) + i) * 1024 + n0 + (tx<<2) + j], acc[i][j]);
}

// ---------------- proj2: kT (0-63), vp (64-127), ksb (128-131) ----------------
__global__ void proj2_kernel(const float* __restrict__ wq, const float* __restrict__ wo,
                             const float* __restrict__ bq) {
    int bid = blockIdx.x;
    int tid = threadIdx.x;

    if (bid >= 128) {         // ksb: bq . k
        int warp = tid >> 5, lane = tid & 31;
        int base = (bid - 128) * 32 + warp * 4;
        for (int r = 0; r < 4; r++) {
            int row = base + r;
            const float4* kr = (const float4*)&g_kv[(size_t)row * 1024];
            float s = 0.f;
            #pragma unroll
            for (int i = 0; i < 4; i++) {
                float4 kvv = kr[i*32 + lane];
                float4 bqv = *(const float4*)&bq[(i*32 + lane) << 2];
                s += kvv.x*bqv.x + kvv.y*bqv.y + kvv.z*bqv.z + kvv.w*bqv.w;
            }
            #pragma unroll
            for (int off = 16; off > 0; off >>= 1) s += __shfl_xor_sync(FULLMASK, s, off);
            if (lane == 0) g_ksb[row] = s;
        }
        return;
    }

    __shared__ float As[16][68];
    __shared__ float Bs[16][68];
    bool isK = bid < 64;
    int local = bid & 63;
    int n0 = (local & 7) * 64;
    int m0 = ((local >> 3) & 1) * 64;
    int k0base = (local >> 4) * 128;        // split-K 4
    const float* A = isK ? g_kv : (g_kv + 512);
    const float* B = isK ? wq : wo;
    int tx = tid & 15, ty = tid >> 4;

    float acc[4][4];
    #pragma unroll
    for (int i = 0; i < 4; i++)
        #pragma unroll
        for (int j = 0; j < 4; j++) acc[i][j] = 0.f;

    for (int k0 = k0base; k0 < k0base + 128; k0 += 16) {
        {
            int mm = tid >> 2, kb = (tid & 3) << 2;
            float4 av = *(const float4*)&A[(size_t)(m0 + mm) * 1024 + k0 + kb];
            As[kb+0][mm] = av.x; As[kb+1][mm] = av.y;
            As[kb+2][mm] = av.z; As[kb+3][mm] = av.w;
        }
        if (isK) {            // B = wq: Bs[k][n] = B[k*512 + n]
            int kk = tid >> 4, nb = (tid & 15) << 2;
            float4 bv = *(const float4*)&B[(size_t)(k0 + kk) * 512 + n0 + nb];
            *(float4*)&Bs[kk][nb] = bv;
        } else {              // B = wo^T
            int nn = tid >> 2, kb = (tid & 3) << 2;
            float4 bv = *(const float4*)&B[(size_t)(n0 + nn) * 512 + k0 + kb];
            Bs[kb+0][nn] = bv.x; Bs[kb+1][nn] = bv.y;
            Bs[kb+2][nn] = bv.z; Bs[kb+3][nn] = bv.w;
        }
        __syncthreads();
        #pragma unroll
        for (int kk = 0; kk < 16; kk++) {
            float4 a4 = *(const float4*)&As[kk][ty << 2];
            float4 b4 = *(const float4*)&Bs[kk][tx << 2];
            float a[4] = {a4.x, a4.y, a4.z, a4.w};
            float bb[4] = {b4.x, b4.y, b4.z, b4.w};
            #pragma unroll
            for (int i = 0; i < 4; i++)
                #pragma unroll
                for (int j = 0; j < 4; j++)
                    acc[i][j] += a[i] * bb[j];
        }
        __syncthreads();
    }
    #pragma unroll
    for (int i = 0; i < 4; i++)
        #pragma unroll
        for (int j = 0; j < 4; j++) {
            int m = m0 + (ty << 2) + i, n = n0 + (tx << 2) + j;
            if (isK) atomicAdd(&g_kpT[(size_t)n * 128 + m], acc[i][j]);
            else     atomicAdd(&g_vp [(size_t)m * 512 + n], acc[i][j]);
        }
}

// ---------------- fused normalize + attention (tf32 mma) + residual ----------------
// block per (b, t, 32-hw tile); 256 threads (8 warps); ~109KB smem -> 2 CTAs/SM
__global__ void __launch_bounds__(256) attn_kernel(
    const float* __restrict__ x, const float* __restrict__ gamma,
    const float* __restrict__ beta, const float* __restrict__ bo,
    float* __restrict__ out) {
    extern __shared__ float sh[];
    float* sh_hf = sh;                       // 32 x STR  (h tf32, later o fp32)
    uint*  sh_hu = (uint*)sh;
    float* sh_kf = sh + 32 * STR;            // kT 128xKSTR / v 64xVSTR (tf32)
    uint*  sh_ku = (uint*)sh_kf;
    float* sh_sf = sh_kf + 128 * KSTR;       // 32 x SSTR (scores fp32 -> weights tf32)
    uint*  sh_su = (uint*)sh_sf;
    __shared__ float sksb[64];

    int bi = blockIdx.x;
    int tile = bi & 31, t = 15 - ((bi >> 5) & 15), b = bi >> 9;
    int hw0 = tile * 32;
    int tid = threadIdx.x;
    const int L  = (t + 1) * 4;
    const int L8 = (L + 7) & ~7;

    // ---- prefetch kT chunk 0 into registers ----
    float4 pre[8];
    #pragma unroll
    for (int i = 0; i < 8; i++) {
        int idx = i * 256 + tid;
        int cc = idx >> 4, sf = (idx & 15) << 2;
        if (sf < L8) pre[i] = *(const float4*)&g_kpT[(size_t)cc * 128 + b * 64 + sf];
    }
    if (tid < 64) sksb[tid] = g_ksb[b * 64 + tid];

    // ---- stage normalized h (tf32) ----
    {
        const float* mub = g_mu   + b * 512 + t;
        const float* rsb = g_rstd + b * 512 + t;
        #pragma unroll
        for (int it = 0; it < 16; it++) {
            int lin = it * 256 + tid;
            int c  = lin >> 3;
            int hw = (lin & 7) << 2;
            float4 xv = *(const float4*)(x + (size_t)(((b*Cc + c)*Tt + t)) * HWp + hw0 + hw);
            int g = c >> 4;
            float scl = rsb[g * 16] * gamma[c];
            float bia = beta[c] - mub[g * 16] * scl;
            sh_hu[(hw+0)*STR + c] = tf32r(xv.x * scl + bia);
            sh_hu[(hw+1)*STR + c] = tf32r(xv.y * scl + bia);
            sh_hu[(hw+2)*STR + c] = tf32r(xv.z * scl + bia);
            sh_hu[(hw+3)*STR + c] = tf32r(xv.w * scl + bia);
        }
    }
    __syncthreads();

    int warp = tid >> 5, lane = tid & 31;
    int grp = lane >> 2, tig = lane & 3;

    // ================= scores: S = h @ kT (tf32 mma) =================
    {
        int qw = warp >> 2, sw = warp & 3;
        int q0 = qw * 16;
        int s0a = sw * 16, s0b = sw * 16 + 8;
        bool act0 = s0a < L, act1 = s0b < L;
        float4 C0 = {0,0,0,0}, C1 = {0,0,0,0};

        for (int ch = 0; ch < 4; ch++) {
            // store prefetched kT chunk (tf32)
            #pragma unroll
            for (int i = 0; i < 8; i++) {
                int idx = i * 256 + tid;
                int cc = idx >> 4, sf = (idx & 15) << 2;
                if (sf < L8) {
                    sh_ku[cc*KSTR + sf + 0] = tf32r(pre[i].x);
                    sh_ku[cc*KSTR + sf + 1] = tf32r(pre[i].y);
                    sh_ku[cc*KSTR + sf + 2] = tf32r(pre[i].z);
                    sh_ku[cc*KSTR + sf + 3] = tf32r(pre[i].w);
                }
            }
            __syncthreads();
            // prefetch next chunk (kT ch+1, or v chunk 0 on last)
            if (ch < 3) {
                #pragma unroll
                for (int i = 0; i < 8; i++) {
                    int idx = i * 256 + tid;
                    int cc = idx >> 4, sf = (idx & 15) << 2;
                    if (sf < L8)
                        pre[i] = *(const float4*)&g_kpT[(size_t)(128*(ch+1) + cc) * 128 + b * 64 + sf];
                }
            } else {
                #pragma unroll
                for (int i = 0; i < 8; i++) {
                    int idx = i * 256 + tid;
                    int s = idx >> 5, col = (idx & 31) << 2;
                    if (s < L8)
                        pre[i] = *(const float4*)&g_vp[(size_t)(b * 64 + s) * 512 + col];
                }
            }
            if (act0) {
                int c0 = ch * 128;
                #pragma unroll
                for (int k8 = 0; k8 < 16; k8++) {
                    int cb = k8 * 8;
                    uint a0 = sh_hu[(q0+grp  )*STR + c0 + cb + tig];
                    uint a1 = sh_hu[(q0+grp+8)*STR + c0 + cb + tig];
                    uint a2 = sh_hu[(q0+grp  )*STR + c0 + cb + tig + 4];
                    uint a3 = sh_hu[(q0+grp+8)*STR + c0 + cb + tig + 4];
                    uint b0 = sh_ku[(cb+tig  )*KSTR + s0a + grp];
                    uint b1 = sh_ku[(cb+tig+4)*KSTR + s0a + grp];
                    mma_tf32(C0, a0, a1, a2, a3, b0, b1);
                    if (act1) {
                        uint b2 = sh_ku[(cb+tig  )*KSTR + s0b + grp];
                        uint b3 = sh_ku[(cb+tig+4)*KSTR + s0b + grp];
                        mma_tf32(C1, a0, a1, a2, a3, b2, b3);
                    }
                }
            }
            __syncthreads();
        }
        // epilogue -> sh_s (fp32, +bias, *scale)
        if (act0) {
            int s = s0a + 2 * tig;
            if (s < L) {
                float kb = sksb[s];
                sh_sf[(q0+grp  )*SSTR + s] = (C0.x + kb) * SCALE;
                sh_sf[(q0+grp+8)*SSTR + s] = (C0.z + kb) * SCALE;
            }
            if (s + 1 < L) {
                float kb = sksb[s+1];
                sh_sf[(q0+grp  )*SSTR + s + 1] = (C0.y + kb) * SCALE;
                sh_sf[(q0+grp+8)*SSTR + s + 1] = (C0.w + kb) * SCALE;
            }
            if (act1) {
                int s2 = s0b + 2 * tig;
                if (s2 < L) {
                    float kb = sksb[s2];
                    sh_sf[(q0+grp  )*SSTR + s2] = (C1.x + kb) * SCALE;
                    sh_sf[(q0+grp+8)*SSTR + s2] = (C1.z + kb) * SCALE;
                }
                if (s2 + 1 < L) {
                    float kb = sksb[s2+1];
                    sh_sf[(q0+grp  )*SSTR + s2 + 1] = (C1.y + kb) * SCALE;
                    sh_sf[(q0+grp+8)*SSTR + s2 + 1] = (C1.w + kb) * SCALE;
                }
            }
        }
    }
    __syncthreads();

    // ================= softmax (warp = 4 rows), write tf32 weights =================
    for (int r = 0; r < 4; r++) {
        int q = warp * 4 + r;
        float v0 = (lane      < L) ? sh_sf[q * SSTR + lane     ] : -INFINITY;
        float v1 = (lane + 32 < L) ? sh_sf[q * SSTR + lane + 32] : -INFINITY;
        float mx = fmaxf(v0, v1);
        #pragma unroll
        for (int off = 16; off > 0; off >>= 1) mx = fmaxf(mx, __shfl_xor_sync(FULLMASK, mx, off));
        float e0 = __expf(v0 - mx), e1 = __expf(v1 - mx);
        float ds = e0 + e1;
        #pragma unroll
        for (int off = 16; off > 0; off >>= 1) ds += __shfl_xor_sync(FULLMASK, ds, off);
        float inv = 1.f / ds;
        if (lane      < L8) sh_su[q * SSTR + lane     ] = (lane      < L) ? tf32r(e0 * inv) : 0u;
        if (lane + 32 < L8) sh_su[q * SSTR + lane + 32] = (lane + 32 < L) ? tf32r(e1 * inv) : 0u;
    }
    __syncthreads();

    // ================= combine: O = W @ v' (tf32 mma) =================
    {
        int qw = warp >> 2, cw = warp & 3;
        int q0 = qw * 16;
        const int kmax = L8 >> 3;

        for (int ch = 0; ch < 4; ch++) {
            // store prefetched v chunk (tf32)
            #pragma unroll
            for (int i = 0; i < 8; i++) {
                int idx = i * 256 + tid;
                int s = idx >> 5, col = (idx & 31) << 2;
                if (s < L8) {
                    sh_ku[s*VSTR + col + 0] = tf32r(pre[i].x);
                    sh_ku[s*VSTR + col + 1] = tf32r(pre[i].y);
                    sh_ku[s*VSTR + col + 2] = tf32r(pre[i].z);
                    sh_ku[s*VSTR + col + 3] = tf32r(pre[i].w);
                }
            }
            __syncthreads();
            if (ch < 3) {
                #pragma unroll
                for (int i = 0; i < 8; i++) {
                    int idx = i * 256 + tid;
                    int s = idx >> 5, col = (idx & 31) << 2;
                    if (s < L8)
                        pre[i] = *(const float4*)&g_vp[(size_t)(b * 64 + s) * 512 + 128*(ch+1) + col];
                }
            }
            float4 D[4];
            #pragma unroll
            for (int nt = 0; nt < 4; nt++) D[nt] = make_float4(0.f, 0.f, 0.f, 0.f);

            #pragma unroll 4
            for (int k8 = 0; k8 < kmax; k8++) {
                int kb = k8 * 8;
                uint a0 = sh_su[(q0+grp  )*SSTR + kb + tig];
                uint a1 = sh_su[(q0+grp+8)*SSTR + kb + tig];
                uint a2 = sh_su[(q0+grp  )*SSTR + kb + tig + 4];
                uint a3 = sh_su[(q0+grp+8)*SSTR + kb + tig + 4];
                #pragma unroll
                for (int nt = 0; nt < 4; nt++) {
                    int n0 = cw * 32 + nt * 8;
                    uint b0 = sh_ku[(kb+tig  )*VSTR + n0 + grp];
                    uint b1 = sh_ku[(kb+tig+4)*VSTR + n0 + grp];
                    mma_tf32(D[nt], a0, a1, a2, a3, b0, b1);
                }
            }
            // epilogue -> sh_h (fp32 o)
            int c0 = ch * 128;
            #pragma unroll
            for (int nt = 0; nt < 4; nt++) {
                int col = cw * 32 + nt * 8 + 2 * tig;
                float2 r0 = {D[nt].x, D[nt].y};
                float2 r1 = {D[nt].z, D[nt].w};
                *(float2*)&sh_hf[(q0+grp  )*STR + c0 + col] = r0;
                *(float2*)&sh_hf[(q0+grp+8)*STR + c0 + col] = r1;
            }
            __syncthreads();
        }
    }

    // ---- out = x + o + bo ----
    #pragma unroll
    for (int it = 0; it < 64; it++) {
        int lin = it * 256 + tid;
        int c = lin >> 5, hw = lin & 31;
        size_t gidx = (size_t)(((b*Cc + c)*Tt + t)) * HWp + hw0 + hw;
        out[gidx] = x[gidx] + sh_hf[hw * STR + c] + bo[c];
    }
}

// ---------------- launch ----------------
extern "C" void kernel_launch(void* const* d_in, const int* in_sizes, int n_in,
                              void* d_out, int out_size) {
    const float* x       = (const float*)d_in[0];
    const float* context = (const float*)d_in[1];
    const float* gamma   = (const float*)d_in[2];
    const float* beta    = (const float*)d_in[3];
    const float* wq      = (const float*)d_in[4];
    const float* bq      = (const float*)d_in[5];
    const float* wkv     = (const float*)d_in[6];
    const float* bkv     = (const float*)d_in[7];
    const float* wo      = (const float*)d_in[8];
    const float* bo      = (const float*)d_in[9];
    float* out = (float*)d_out;

    const int SMEM_BYTES = (32*STR + 128*KSTR + 32*SSTR) * 4;   // 111616
    cudaFuncSetAttribute(attn_kernel, cudaFuncAttributeMaxDynamicSharedMemorySize, SMEM_BYTES);

    seed_kernel<<<1024, 256>>>(bkv);
    gn_stats_kernel<<<1024, 256>>>(x);
    kv_gemm<<<dim3(16, 2, 8), 256>>>(context, wkv);
    proj2_kernel<<<132, 256>>>(wq, wo, bq);
    attn_kernel<<<Bz * Tt * 32, 256, SMEM_BYTES>>>(x, gamma, beta, bo, out);
}

// round 8
// speedup vs baseline: 1.9762x; 1.4027x over previous
#include <cuda_runtime.h>
#include <cuda_bf16.h>
#include <math.h>

#define Bz   2
#define Cc   512
#define Tt   16
#define HWp  1024
#define EPS  1e-5f
#define SCALE 0.04419417382415922f  // 512^-0.5
#define FULLMASK 0xffffffffu
#define HSTR 260    // h row stride in uints (bf16x2 pairs); 260%32=4 -> conflict-free A frags
#define KST2 72     // kT chunk pair-row stride (uints); 72%32=8 -> conflict-free B frags
#define VST2 136    // v chunk pair-row stride (uints); 136%32=8
#define SSTR 68     // fp32 score row stride
#define WST  36     // packed weight row stride (uints); 36%32=4

typedef unsigned int uint;

// ---------------- helpers ----------------
__device__ __forceinline__ uint packbf(float lo, float hi) {
    uint r; asm("cvt.rn.bf16x2.f32 %0, %1, %2;" : "=r"(r) : "f"(hi), "f"(lo)); return r;
}
__device__ __forceinline__ void mma_bf16(float4& d, uint a0, uint a1, uint a2, uint a3,
                                         uint b0, uint b1) {
    asm volatile("mma.sync.aligned.m16n8k16.row.col.f32.bf16.bf16.f32 "
                 "{%0,%1,%2,%3}, {%4,%5,%6,%7}, {%8,%9}, {%0,%1,%2,%3};"
                 : "+f"(d.x), "+f"(d.y), "+f"(d.z), "+f"(d.w)
                 : "r"(a0), "r"(a1), "r"(a2), "r"(a3), "r"(b0), "r"(b1));
}

// ---------------- scratch ----------------
__device__ float g_mu  [Bz * 32 * Tt];
__device__ float g_rstd[Bz * 32 * Tt];
__device__ float g_kv  [128 * 1024];      // [b*64+s][2C]
__device__ float g_kpT [512 * 128];       // fp32 [c][b*64+s]
__device__ float g_vp  [128 * 512];       // fp32 [b*64+s][c]
__device__ uint  g_kpTb[256 * 128];       // bf16x2 pairs over c: [cpair][b*64+s]
__device__ uint  g_vpb [64 * 512];        // bf16x2 pairs over s: [b*32+spair][c]
__device__ float g_ksb [128];

// ---------------- gn stats + seed (merged) ----------------
__global__ void gn_seed_kernel(const float* __restrict__ x, const float* __restrict__ bkv) {
    int idx = blockIdx.x;                 // b*512 + g*16 + t
    int tid = threadIdx.x;
    {
        int i = idx * 256 + tid;
        if (i < 131072)       g_kv[i]         = bkv[i & 1023];
        else if (i < 196608)  g_kpT[i-131072] = 0.f;
        else                  g_vp[i-196608]  = 0.f;
    }
    int b = idx >> 9, g = (idx >> 4) & 31, t = idx & 15;
    float s = 0.f, sq = 0.f;
    for (int ci = 0; ci < 16; ci++) {
        const float4* row = (const float4*)(x + (size_t)(((b*Cc + g*16 + ci)*Tt + t)) * HWp);
        float4 v = row[tid];
        s  += v.x + v.y + v.z + v.w;
        sq += v.x*v.x + v.y*v.y + v.z*v.z + v.w*v.w;
    }
    __shared__ float s1[256], s2[256];
    s1[tid] = s; s2[tid] = sq;
    __syncthreads();
    for (int st = 128; st > 0; st >>= 1) {
        if (tid < st) { s1[tid] += s1[tid + st]; s2[tid] += s2[tid + st]; }
        __syncthreads();
    }
    if (tid == 0) {
        const float invN = 1.f / 16384.f;
        float mu  = s1[0] * invN;
        float var = s2[0] * invN - mu * mu;
        g_mu[idx] = mu;
        g_rstd[idx] = rsqrtf(var + EPS);
    }
}

// ---------------- kv = context @ wkv^T (split-K 8, atomic) ----------------
__global__ void kv_gemm(const float* __restrict__ A, const float* __restrict__ B) {
    __shared__ float As[16][68];
    __shared__ float Bs[16][68];
    int m0 = blockIdx.y * 64, n0 = blockIdx.x * 64;
    int k0base = blockIdx.z * 128;
    int tid = threadIdx.x;
    int tx = tid & 15, ty = tid >> 4;

    float acc[4][4];
    #pragma unroll
    for (int i = 0; i < 4; i++)
        #pragma unroll
        for (int j = 0; j < 4; j++) acc[i][j] = 0.f;

    for (int k0 = k0base; k0 < k0base + 128; k0 += 16) {
        {
            int mm = tid >> 2, kb = (tid & 3) << 2;
            float4 av = *(const float4*)&A[(size_t)(m0 + mm) * 1024 + k0 + kb];
            As[kb+0][mm] = av.x; As[kb+1][mm] = av.y;
            As[kb+2][mm] = av.z; As[kb+3][mm] = av.w;
        }
        {
            int nn = tid >> 2, kb = (tid & 3) << 2;
            float4 bv = *(const float4*)&B[(size_t)(n0 + nn) * 1024 + k0 + kb];
            Bs[kb+0][nn] = bv.x; Bs[kb+1][nn] = bv.y;
            Bs[kb+2][nn] = bv.z; Bs[kb+3][nn] = bv.w;
        }
        __syncthreads();
        #pragma unroll
        for (int kk = 0; kk < 16; kk++) {
            float4 a4 = *(const float4*)&As[kk][ty << 2];
            float4 b4 = *(const float4*)&Bs[kk][tx << 2];
            float a[4] = {a4.x, a4.y, a4.z, a4.w};
            float bb[4] = {b4.x, b4.y, b4.z, b4.w};
            #pragma unroll
            for (int i = 0; i < 4; i++)
                #pragma unroll
                for (int j = 0; j < 4; j++)
                    acc[i][j] += a[i] * bb[j];
        }
        __syncthreads();
    }
    #pragma unroll
    for (int i = 0; i < 4; i++)
        #pragma unroll
        for (int j = 0; j < 4; j++)
            atomicAdd(&g_kv[(size_t)(m0 + (ty<<2) + i) * 1024 + n0 + (tx<<2) + j], acc[i][j]);
}

// ---------------- proj2: kT (0-127), vp (128-255), ksb (256-259); split-K 8 ----------------
__global__ void proj2_kernel(const float* __restrict__ wq, const float* __restrict__ wo,
                             const float* __restrict__ bq) {
    int bid = blockIdx.x;
    int tid = threadIdx.x;

    if (bid >= 256) {         // ksb: bq . k
        int warp = tid >> 5, lane = tid & 31;
        int base = (bid - 256) * 32 + warp * 4;
        for (int r = 0; r < 4; r++) {
            int row = base + r;
            const float4* kr = (const float4*)&g_kv[(size_t)row * 1024];
            float s = 0.f;
            #pragma unroll
            for (int i = 0; i < 4; i++) {
                float4 kvv = kr[i*32 + lane];
                float4 bqv = *(const float4*)&bq[(i*32 + lane) << 2];
                s += kvv.x*bqv.x + kvv.y*bqv.y + kvv.z*bqv.z + kvv.w*bqv.w;
            }
            #pragma unroll
            for (int off = 16; off > 0; off >>= 1) s += __shfl_xor_sync(FULLMASK, s, off);
            if (lane == 0) g_ksb[row] = s;
        }
        return;
    }

    __shared__ float As[16][68];
    __shared__ float Bs[16][68];
    bool isK = bid < 128;
    int local = bid & 127;
    int n0 = (local & 7) * 64;
    int m0 = ((local >> 3) & 1) * 64;
    int k0base = (local >> 4) * 64;         // split-K 8
    const float* A = isK ? g_kv : (g_kv + 512);
    const float* B = isK ? wq : wo;
    int tx = tid & 15, ty = tid >> 4;

    float acc[4][4];
    #pragma unroll
    for (int i = 0; i < 4; i++)
        #pragma unroll
        for (int j = 0; j < 4; j++) acc[i][j] = 0.f;

    for (int k0 = k0base; k0 < k0base + 64; k0 += 16) {
        {
            int mm = tid >> 2, kb = (tid & 3) << 2;
            float4 av = *(const float4*)&A[(size_t)(m0 + mm) * 1024 + k0 + kb];
            As[kb+0][mm] = av.x; As[kb+1][mm] = av.y;
            As[kb+2][mm] = av.z; As[kb+3][mm] = av.w;
        }
        if (isK) {            // B = wq: Bs[k][n] = B[k*512 + n]
            int kk = tid >> 4, nb = (tid & 15) << 2;
            float4 bv = *(const float4*)&B[(size_t)(k0 + kk) * 512 + n0 + nb];
            *(float4*)&Bs[kk][nb] = bv;
        } else {              // B = wo^T
            int nn = tid >> 2, kb = (tid & 3) << 2;
            float4 bv = *(const float4*)&B[(size_t)(n0 + nn) * 512 + k0 + kb];
            Bs[kb+0][nn] = bv.x; Bs[kb+1][nn] = bv.y;
            Bs[kb+2][nn] = bv.z; Bs[kb+3][nn] = bv.w;
        }
        __syncthreads();
        #pragma unroll
        for (int kk = 0; kk < 16; kk++) {
            float4 a4 = *(const float4*)&As[kk][ty << 2];
            float4 b4 = *(const float4*)&Bs[kk][tx << 2];
            float a[4] = {a4.x, a4.y, a4.z, a4.w};
            float bb[4] = {b4.x, b4.y, b4.z, b4.w};
            #pragma unroll
            for (int i = 0; i < 4; i++)
                #pragma unroll
                for (int j = 0; j < 4; j++)
                    acc[i][j] += a[i] * bb[j];
        }
        __syncthreads();
    }
    #pragma unroll
    for (int i = 0; i < 4; i++)
        #pragma unroll
        for (int j = 0; j < 4; j++) {
            int m = m0 + (ty << 2) + i, n = n0 + (tx << 2) + j;
            if (isK) atomicAdd(&g_kpT[(size_t)n * 128 + m], acc[i][j]);
            else     atomicAdd(&g_vp [(size_t)m * 512 + n], acc[i][j]);
        }
}

// ---------------- cvt: fp32 k'/v' -> packed bf16x2 ----------------
__global__ void cvt_kernel() {
    int j = blockIdx.x * 256 + threadIdx.x;   // 0..65535
    if (j < 32768) {
        int cp = j >> 7, scol = j & 127;
        g_kpTb[j] = packbf(g_kpT[(2*cp)*128 + scol], g_kpT[(2*cp+1)*128 + scol]);
    } else {
        int j2 = j - 32768;
        int spg = j2 >> 9, c = j2 & 511;      // spg = b*32 + spair
        int b = spg >> 5, sp = spg & 31;
        int r0 = ((b*64 + 2*sp)) * 512 + c;
        g_vpb[j2] = packbf(g_vp[r0], g_vp[r0 + 512]);
    }
}

// ---------------- fused normalize + attention (bf16 mma) + residual ----------------
// block per (b, t, 32-hw tile); 256 threads (8 warps); ~65KB smem -> 3 CTAs/SM
__global__ void __launch_bounds__(256, 3) attn_kernel(
    const float* __restrict__ x, const float* __restrict__ gamma,
    const float* __restrict__ beta, const float* __restrict__ bo,
    float* __restrict__ out) {
    extern __shared__ uint shu[];
    uint* sh_hu = shu;                              // 32 x HSTR  (bf16x2 h pairs over c)
    __nv_bfloat16* sh_hb = (__nv_bfloat16*)shu;     // same, bf16 view (row stride 2*HSTR)
    uint* sh_ku  = shu + 32 * HSTR;                 // kT 64xKST2 / v 32xVST2
    float* sh_sf = (float*)(sh_ku + 64 * KST2);     // 32 x SSTR fp32 scores
    uint* sw_u   = (uint*)(sh_sf + 32 * SSTR);      // 32 x WST packed weights
    __shared__ float sksb[64];

    int bi = blockIdx.x;
    int tile = bi & 31, t = 15 - ((bi >> 5) & 15), b = bi >> 9;
    int hw0 = tile * 32;
    int tid = threadIdx.x;
    const int L   = (t + 1) * 4;
    const int L8  = (L + 7) & ~7;
    const int L16 = (L + 15) & ~15;

    // ---- prefetch kT chunk 0 (packed bf16x2) ----
    uint4 pre[4];
    #pragma unroll
    for (int i = 0; i < 4; i++) {
        int idx = i * 256 + tid;                  // 0..1023
        int cc = idx >> 4, sfu = (idx & 15) << 2;
        if (sfu < L8) pre[i] = *(const uint4*)&g_kpTb[(size_t)cc * 128 + b * 64 + sfu];
    }
    if (tid < 64) sksb[tid] = g_ksb[b * 64 + tid];

    // ---- stage normalized h (bf16) ----
    {
        const float* mub = g_mu   + b * 512 + t;
        const float* rsb = g_rstd + b * 512 + t;
        #pragma unroll
        for (int it = 0; it < 16; it++) {
            int lin = it * 256 + tid;
            int c  = lin >> 3;
            int hw = (lin & 7) << 2;
            float4 xv = *(const float4*)(x + (size_t)(((b*Cc + c)*Tt + t)) * HWp + hw0 + hw);
            int g = c >> 4;
            float scl = rsb[g * 16] * gamma[c];
            float bia = beta[c] - mub[g * 16] * scl;
            sh_hb[(hw+0)*(2*HSTR) + c] = __float2bfloat16(xv.x * scl + bia);
            sh_hb[(hw+1)*(2*HSTR) + c] = __float2bfloat16(xv.y * scl + bia);
            sh_hb[(hw+2)*(2*HSTR) + c] = __float2bfloat16(xv.z * scl + bia);
            sh_hb[(hw+3)*(2*HSTR) + c] = __float2bfloat16(xv.w * scl + bia);
        }
    }
    __syncthreads();

    int warp = tid >> 5, lane = tid & 31;
    int grp = lane >> 2, tig = lane & 3;

    // ================= scores: S = h @ kT (bf16 m16n8k16) =================
    {
        int qw = warp >> 2, sw = warp & 3;
        int q0 = qw * 16;
        int s0a = sw * 16, s0b = sw * 16 + 8;
        bool act0 = s0a < L, act1 = s0b < L;
        float4 C0 = {0,0,0,0}, C1 = {0,0,0,0};

        for (int ch = 0; ch < 4; ch++) {
            // store prefetched kT chunk
            #pragma unroll
            for (int i = 0; i < 4; i++) {
                int idx = i * 256 + tid;
                int cc = idx >> 4, sfu = (idx & 15) << 2;
                if (sfu < L8) *(uint4*)&sh_ku[cc * KST2 + sfu] = pre[i];
            }
            __syncthreads();
            // prefetch next (kT ch+1, or v chunk 0 on last)
            if (ch < 3) {
                #pragma unroll
                for (int i = 0; i < 4; i++) {
                    int idx = i * 256 + tid;
                    int cc = idx >> 4, sfu = (idx & 15) << 2;
                    if (sfu < L8)
                        pre[i] = *(const uint4*)&g_kpTb[(size_t)((ch+1)*64 + cc) * 128 + b * 64 + sfu];
                }
            } else {
                #pragma unroll
                for (int i = 0; i < 4; i++) {
                    int idx = i * 256 + tid;
                    int sp = idx >> 5, cu = (idx & 31) << 2;
                    if (sp * 2 < L16)
                        pre[i] = *(const uint4*)&g_vpb[(size_t)(b * 32 + sp) * 512 + cu];
                }
            }
            if (act0) {
                int pb = ch * 64;               // pair base in sh_h
                #pragma unroll
                for (int k8 = 0; k8 < 8; k8++) {
                    int ap = pb + k8 * 8;
                    uint a0 = sh_hu[(q0+grp  )*HSTR + ap + tig];
                    uint a1 = sh_hu[(q0+grp+8)*HSTR + ap + tig];
                    uint a2 = sh_hu[(q0+grp  )*HSTR + ap + tig + 4];
                    uint a3 = sh_hu[(q0+grp+8)*HSTR + ap + tig + 4];
                    uint b0 = sh_ku[(k8*8+tig  )*KST2 + s0a + grp];
                    uint b1 = sh_ku[(k8*8+tig+4)*KST2 + s0a + grp];
                    mma_bf16(C0, a0, a1, a2, a3, b0, b1);
                    if (act1) {
                        uint b2 = sh_ku[(k8*8+tig  )*KST2 + s0b + grp];
                        uint b3 = sh_ku[(k8*8+tig+4)*KST2 + s0b + grp];
                        mma_bf16(C1, a0, a1, a2, a3, b2, b3);
                    }
                }
            }
            __syncthreads();
        }
        // epilogue -> fp32 scores (+bias, *scale)
        if (act0) {
            int s = s0a + 2 * tig;
            if (s < L) {
                float kb = sksb[s];
                sh_sf[(q0+grp  )*SSTR + s] = (C0.x + kb) * SCALE;
                sh_sf[(q0+grp+8)*SSTR + s] = (C0.z + kb) * SCALE;
            }
            if (s + 1 < L) {
                float kb = sksb[s+1];
                sh_sf[(q0+grp  )*SSTR + s + 1] = (C0.y + kb) * SCALE;
                sh_sf[(q0+grp+8)*SSTR + s + 1] = (C0.w + kb) * SCALE;
            }
            if (act1) {
                int s2 = s0b + 2 * tig;
                if (s2 < L) {
                    float kb = sksb[s2];
                    sh_sf[(q0+grp  )*SSTR + s2] = (C1.x + kb) * SCALE;
                    sh_sf[(q0+grp+8)*SSTR + s2] = (C1.z + kb) * SCALE;
                }
                if (s2 + 1 < L) {
                    float kb = sksb[s2+1];
                    sh_sf[(q0+grp  )*SSTR + s2 + 1] = (C1.y + kb) * SCALE;
                    sh_sf[(q0+grp+8)*SSTR + s2 + 1] = (C1.w + kb) * SCALE;
                }
            }
        }
    }
    __syncthreads();

    // ================= softmax (warp = 4 rows) -> packed bf16x2 weights =================
    for (int r = 0; r < 4; r++) {
        int q = warp * 4 + r;
        float v0 = (lane      < L) ? sh_sf[q * SSTR + lane     ] : -INFINITY;
        float v1 = (lane + 32 < L) ? sh_sf[q * SSTR + lane + 32] : -INFINITY;
        float mx = fmaxf(v0, v1);
        #pragma unroll
        for (int off = 16; off > 0; off >>= 1) mx = fmaxf(mx, __shfl_xor_sync(FULLMASK, mx, off));
        float e0 = __expf(v0 - mx), e1 = __expf(v1 - mx);
        float ds = e0 + e1;
        #pragma unroll
        for (int off = 16; off > 0; off >>= 1) ds += __shfl_xor_sync(FULLMASK, ds, off);
        float inv = 1.f / ds;
        float we = e0 * inv, wo_ = e1 * inv;     // s=lane, s=lane+32 (0 beyond L)
        // gather pair (2p, 2p+1) into lane p
        int i0 = (2 * lane) & 31, i1 = (2 * lane + 1) & 31;
        float alo = __shfl_sync(FULLMASK, we,  i0), blo = __shfl_sync(FULLMASK, we,  i1);
        float ahi = __shfl_sync(FULLMASK, wo_, i0), bhi = __shfl_sync(FULLMASK, wo_, i1);
        float wa = lane < 16 ? alo : ahi;
        float wb = lane < 16 ? blo : bhi;
        sw_u[q * WST + lane] = packbf(wa, wb);
    }
    __syncthreads();

    // ================= combine: O = W @ v' (bf16 m16n8k16), fused epilogue =================
    {
        int qw = warp >> 2, cw = warp & 3;
        int q0 = qw * 16;
        const int kmax = L16 >> 4;

        for (int ch = 0; ch < 4; ch++) {
            // store prefetched v chunk (pair rows up to L16/2: mma reads that far)
            #pragma unroll
            for (int i = 0; i < 4; i++) {
                int idx = i * 256 + tid;
                int sp = idx >> 5, cu = (idx & 31) << 2;
                if (sp * 2 < L16) *(uint4*)&sh_ku[sp * VST2 + cu] = pre[i];
            }
            __syncthreads();
            if (ch < 3) {
                #pragma unroll
                for (int i = 0; i < 4; i++) {
                    int idx = i * 256 + tid;
                    int sp = idx >> 5, cu = (idx & 31) << 2;
                    if (sp * 2 < L16)
                        pre[i] = *(const uint4*)&g_vpb[(size_t)(b * 32 + sp) * 512 + (ch+1)*128 + cu];
                }
            }
            float4 D[4];
            #pragma unroll
            for (int nt = 0; nt < 4; nt++) D[nt] = make_float4(0.f, 0.f, 0.f, 0.f);

            #pragma unroll 4
            for (int k8 = 0; k8 < kmax; k8++) {
                int sp = k8 * 8;
                uint a0 = sw_u[(q0+grp  )*WST + sp + tig];
                uint a1 = sw_u[(q0+grp+8)*WST + sp + tig];
                uint a2 = sw_u[(q0+grp  )*WST + sp + tig + 4];
                uint a3 = sw_u[(q0+grp+8)*WST + sp + tig + 4];
                #pragma unroll
                for (int nt = 0; nt < 4; nt++) {
                    int n0c = cw * 32 + nt * 8;
                    uint b0 = sh_ku[(sp+tig  )*VST2 + n0c + grp];
                    uint b1 = sh_ku[(sp+tig+4)*VST2 + n0c + grp];
                    mma_bf16(D[nt], a0, a1, a2, a3, b0, b1);
                }
            }
            // fused epilogue: out = x + o + bo directly from fragments
            int hwA = hw0 + q0 + grp;
            #pragma unroll
            for (int nt = 0; nt < 4; nt++) {
                int c0 = ch*128 + cw*32 + nt*8 + 2*tig;
                float bo0 = bo[c0], bo1 = bo[c0 + 1];
                size_t gA0 = (size_t)(((b*Cc + c0  )*Tt + t)) * HWp + hwA;
                size_t gA1 = (size_t)(((b*Cc + c0+1)*Tt + t)) * HWp + hwA;
                out[gA0]     = x[gA0]     + D[nt].x + bo0;
                out[gA1]     = x[gA1]     + D[nt].y + bo1;
                out[gA0 + 8] = x[gA0 + 8] + D[nt].z + bo0;   // hw row +8
                out[gA1 + 8] = x[gA1 + 8] + D[nt].w + bo1;
            }
            __syncthreads();
        }
    }
}

// ---------------- launch ----------------
extern "C" void kernel_launch(void* const* d_in, const int* in_sizes, int n_in,
                              void* d_out, int out_size) {
    const float* x       = (const float*)d_in[0];
    const float* context = (const float*)d_in[1];
    const float* gamma   = (const float*)d_in[2];
    const float* beta    = (const float*)d_in[3];
    const float* wq      = (const float*)d_in[4];
    const float* bq      = (const float*)d_in[5];
    const float* wkv     = (const float*)d_in[6];
    const float* bkv     = (const float*)d_in[7];
    const float* wo      = (const float*)d_in[8];
    const float* bo      = (const float*)d_in[9];
    float* out = (float*)d_out;

    const int SMEM_BYTES = (32*HSTR + 64*KST2 + 32*SSTR + 32*WST) * 4;   // 65024
    cudaFuncSetAttribute(attn_kernel, cudaFuncAttributeMaxDynamicSharedMemorySize, SMEM_BYTES);

    gn_seed_kernel<<<1024, 256>>>(x, bkv);
    kv_gemm<<<dim3(16, 2, 8), 256>>>(context, wkv);
    proj2_kernel<<<260, 256>>>(wq, wo, bq);
    cvt_kernel<<<256, 256>>>();
    attn_kernel<<<Bz * Tt * 32, 256, SMEM_BYTES>>>(x, gamma, beta, bo, out);
}